// round 17
// baseline (speedup 1.0000x reference)
#include <cuda_runtime.h>
#include <cuda_fp16.h>

#define BB 4
#define NN 512
#define DD 256

// ---------------- scratch (static device globals: allocation-free) ----------
__device__ __align__(16) __half g_q[BB * NN * DD];     // 1 MB
__device__ __align__(16) __half g_k[BB * NN * DD];     // 1 MB
__device__ __align__(16) float  g_wei[BB * NN * NN];   // 4 MB (raw scores)
__device__ __align__(16) __half g_xh[BB * NN * DD];    // 1 MB (X in fp16)
__device__ __align__(16) __half g_wh[DD * DD];         // Wa_w fp16
__device__ __align__(16) __half g_uh[DD * DD];         // Ua_w fp16

// ---------------- small PTX helpers ------------------------------------------
__device__ __forceinline__ unsigned tanh_h2(unsigned xi) {
    unsigned yi;
    asm("tanh.approx.f16x2 %0, %1;" : "=r"(yi) : "r"(xi));
    return yi;
}
__device__ __forceinline__ unsigned hadd2_u(unsigned a, unsigned b) {
    unsigned c;
    asm("add.f16x2 %0, %1, %2;" : "=r"(c) : "r"(a), "r"(b));
    return c;
}
__device__ __forceinline__ unsigned hfma2_u(unsigned a, unsigned b, unsigned c) {
    unsigned d;
    asm("fma.rn.f16x2 %0, %1, %2, %3;" : "=r"(d) : "r"(a), "r"(b), "r"(c));
    return d;
}
__device__ __forceinline__ unsigned smem_u32(const void* p) {
    return (unsigned)__cvta_generic_to_shared(p);
}
__device__ __forceinline__ void cp16(void* dst, const void* src) {
    asm volatile("cp.async.cg.shared.global [%0], [%1], 16;"
        :: "r"(smem_u32(dst)), "l"(src));
}
#define CP_COMMIT() asm volatile("cp.async.commit_group;")
#define CP_WAIT0()  asm volatile("cp.async.wait_group 0;")
#define CP_WAIT1()  asm volatile("cp.async.wait_group 1;")

__device__ __forceinline__ void ldsm_x4(unsigned* r, const __half* p) {
    unsigned a = smem_u32(p);
    asm volatile("ldmatrix.sync.aligned.m8n8.x4.shared.b16 {%0,%1,%2,%3}, [%4];"
        : "=r"(r[0]), "=r"(r[1]), "=r"(r[2]), "=r"(r[3]) : "r"(a));
}
__device__ __forceinline__ void ldsm_x4_trans(unsigned* r, const __half* p) {
    unsigned a = smem_u32(p);
    asm volatile("ldmatrix.sync.aligned.m8n8.x4.trans.shared.b16 {%0,%1,%2,%3}, [%4];"
        : "=r"(r[0]), "=r"(r[1]), "=r"(r[2]), "=r"(r[3]) : "r"(a));
}
__device__ __forceinline__ void mma16816(float* c, const unsigned* a,
                                         unsigned b0, unsigned b1) {
    asm volatile("mma.sync.aligned.m16n8k16.row.col.f32.f16.f16.f32 "
        "{%0,%1,%2,%3}, {%4,%5,%6,%7}, {%8,%9}, {%0,%1,%2,%3};"
        : "+f"(c[0]), "+f"(c[1]), "+f"(c[2]), "+f"(c[3])
        : "r"(a[0]), "r"(a[1]), "r"(a[2]), "r"(a[3]), "r"(b0), "r"(b1));
}

// ---------------- kernel 0: fp32 -> fp16 conversions (proven) ----------------
__global__ __launch_bounds__(256) void conv_kernel(
    const float4* __restrict__ X4, const float4* __restrict__ Wa4,
    const float4* __restrict__ Ua4)
{
    int i = blockIdx.x * 256 + threadIdx.x;     // 0 .. 163839
    const float4* src;
    uint2* dst;
    int j;
    if (i < 131072)      { src = X4;  j = i;          dst = (uint2*)g_xh; }
    else if (i < 147456) { src = Wa4; j = i - 131072; dst = (uint2*)g_wh; }
    else                 { src = Ua4; j = i - 147456; dst = (uint2*)g_uh; }
    float4 v = src[j];
    __half2 h01 = __floats2half2_rn(v.x, v.y);
    __half2 h23 = __floats2half2_rn(v.z, v.w);
    uint2 o;
    o.x = *reinterpret_cast<unsigned*>(&h01);
    o.y = *reinterpret_cast<unsigned*>(&h23);
    dst[j] = o;
}

// ---------------- kernel 1: q/k projections via HMMA (proven) ----------------
__global__ __launch_bounds__(256) void proj_mma(
    const float* __restrict__ Wb, const float* __restrict__ Ub)
{
    __shared__ __half As[2][128][40];
    __shared__ __half Bs[2][64][40];

    const __half* A    = g_xh;
    const __half* Bw   = blockIdx.z ? g_uh : g_wh;
    const float*  bias = blockIdx.z ? Ub : Wb;
    __half*       out  = blockIdx.z ? g_k : g_q;

    const int bn = blockIdx.x * 64;
    const int bm = blockIdx.y * 128;
    const int tid = threadIdx.x, warp = tid >> 5, lane = tid & 31;
    const int wm = warp >> 1, wn = warp & 1;
    const int gq = lane >> 2, tq = lane & 3;

    const int ar0 = tid >> 2, aq = tid & 3;
    const int br  = tid >> 2, bq = tid & 3;

    float acc[2][4][4] = {};

    cp16(&As[0][ar0][aq * 8],      &A[(bm + ar0) * DD + aq * 8]);
    cp16(&As[0][ar0 + 64][aq * 8], &A[(bm + ar0 + 64) * DD + aq * 8]);
    cp16(&Bs[0][br][bq * 8],       &Bw[(bn + br) * DD + bq * 8]);
    CP_COMMIT();

    #pragma unroll
    for (int it = 0; it < 8; it++) {
        CP_WAIT0();
        __syncthreads();
        if (it < 7) {
            int nk = (it + 1) * 32, s = (it + 1) & 1;
            cp16(&As[s][ar0][aq * 8],      &A[(bm + ar0) * DD + nk + aq * 8]);
            cp16(&As[s][ar0 + 64][aq * 8], &A[(bm + ar0 + 64) * DD + nk + aq * 8]);
            cp16(&Bs[s][br][bq * 8],       &Bw[(bn + br) * DD + nk + bq * 8]);
            CP_COMMIT();
        }
        const int cur = it & 1;

        #pragma unroll
        for (int ks = 0; ks < 2; ks++) {
            int kc = ks * 16;
            unsigned a[2][4], bf[2][4];
            #pragma unroll
            for (int tm = 0; tm < 2; tm++) {
                int r = wm * 32 + tm * 16 + (lane & 15);
                int c = kc + 8 * (lane >> 4);
                ldsm_x4(a[tm], &As[cur][r][c]);
            }
            #pragma unroll
            for (int tn = 0; tn < 2; tn++) {
                int r = wn * 32 + tn * 16 + (lane & 7) + 8 * (lane >> 4);
                int c = kc + 8 * ((lane >> 3) & 1);
                ldsm_x4(bf[tn], &Bs[cur][r][c]);
            }
            #pragma unroll
            for (int tm = 0; tm < 2; tm++)
                #pragma unroll
                for (int tn8 = 0; tn8 < 4; tn8++)
                    mma16816(acc[tm][tn8], a[tm],
                             bf[tn8 >> 1][(tn8 & 1) * 2],
                             bf[tn8 >> 1][(tn8 & 1) * 2 + 1]);
        }
    }

    #pragma unroll
    for (int tm = 0; tm < 2; tm++) {
        #pragma unroll
        for (int tn8 = 0; tn8 < 4; tn8++) {
            int c = bn + wn * 32 + tn8 * 8 + 2 * tq;
            float2 bv = *(const float2*)&bias[c];
            int r0 = bm + wm * 32 + tm * 16 + gq;
            __half2 h0 = __floats2half2_rn(acc[tm][tn8][0] + bv.x,
                                           acc[tm][tn8][1] + bv.y);
            __half2 h1 = __floats2half2_rn(acc[tm][tn8][2] + bv.x,
                                           acc[tm][tn8][3] + bv.y);
            *(__half2*)&out[r0 * DD + c] = h0;
            *(__half2*)&out[(r0 + 8) * DD + c] = h1;
        }
    }
}

// ---------------- kernel 2: additive-attention scores (proven) ---------------
#define KT 32
#define QB 64
#define QSTAGE 32

__global__ __launch_bounds__(256, 3) void score_kernel(const float* __restrict__ Va)
{
    __shared__ __align__(16) unsigned q_sh[QSTAGE][320];  // 40 KB

    const int tid  = threadIdx.x;
    const int w    = tid >> 5;
    const int lane = tid & 31;
    const int dg   = lane >> 2;
    const int kis  = lane & 3;

    const int b     = blockIdx.z;
    const int k0    = blockIdx.x * KT;
    const int qbase = blockIdx.y * QB;
    const int krow  = k0 + w * 4 + kis;

    unsigned kreg[16];
    {
        const uint4* kp = reinterpret_cast<const uint4*>(
            g_k + ((b * NN + krow) << 8) + dg * 32);
        #pragma unroll
        for (int j = 0; j < 4; j++) {
            uint4 t = kp[j];
            kreg[4*j+0] = t.x; kreg[4*j+1] = t.y;
            kreg[4*j+2] = t.z; kreg[4*j+3] = t.w;
        }
    }
    unsigned vh[16];
    {
        const float4* vp = reinterpret_cast<const float4*>(Va + dg * 32);
        #pragma unroll
        for (int j = 0; j < 8; j++) {
            float4 v = vp[j];
            __half2 a = __floats2half2_rn(v.x, v.y);
            __half2 c = __floats2half2_rn(v.z, v.w);
            vh[2*j]   = *reinterpret_cast<unsigned*>(&a);
            vh[2*j+1] = *reinterpret_cast<unsigned*>(&c);
        }
    }

    for (int qc = 0; qc < QB; qc += QSTAGE) {
        __syncthreads();
        const uint4* gq4 = reinterpret_cast<const uint4*>(
            g_q + ((b * NN + qbase + qc) << 8));
        #pragma unroll
        for (int l = 0; l < 4; l++) {
            int idx = tid + 256 * l;
            int r  = idx >> 5;
            int p4 = idx & 31;
            uint4 v = gq4[(r << 5) + p4];
            *reinterpret_cast<uint4*>(&q_sh[r][(p4 >> 2) * 40 + (p4 & 3) * 4]) = v;
        }
        __syncthreads();

        #pragma unroll 2
        for (int qi = 0; qi < QSTAGE; qi++) {
            const uint4* q4 = reinterpret_cast<const uint4*>(&q_sh[qi][dg * 40]);
            unsigned hacc[4] = {0u, 0u, 0u, 0u};
            #pragma unroll
            for (int j = 0; j < 4; j++) {
                uint4 qv = q4[j];
                unsigned qh[4] = {qv.x, qv.y, qv.z, qv.w};
                #pragma unroll
                for (int u = 0; u < 4; u++) {
                    int i = 4 * j + u;
                    unsigned t = tanh_h2(hadd2_u(qh[u], kreg[i]));
                    hacc[u] = hfma2_u(t, vh[i], hacc[u]);
                }
            }
            float2 f0 = __half22float2(*reinterpret_cast<__half2*>(&hacc[0]));
            float2 f1 = __half22float2(*reinterpret_cast<__half2*>(&hacc[1]));
            float2 f2 = __half22float2(*reinterpret_cast<__half2*>(&hacc[2]));
            float2 f3 = __half22float2(*reinterpret_cast<__half2*>(&hacc[3]));
            float partial = ((f0.x + f0.y) + (f1.x + f1.y))
                          + ((f2.x + f2.y) + (f3.x + f3.y));
            partial += __shfl_xor_sync(0xffffffffu, partial, 16);
            partial += __shfl_xor_sync(0xffffffffu, partial, 8);
            partial += __shfl_xor_sync(0xffffffffu, partial, 4);
            if (dg == 0) {
                g_wei[((b * NN + qbase + qc + qi) << 9) + krow] = partial;
            }
        }
    }
}

// ---------------- kernel 3: FUSED masked-softmax + (wei @ X) -----------------
// out[q][d] = (sum_k e_qk * Xh[k][d]) / (sum_k e_qk),  e = mask ? exp(s) : 0.
// Valid without max-subtraction: |s| <~ 6 in f32. BM=32, BN=64, BK=32;
// grid (4,16,4) = 256 blocks (2 CTA/SM). 3-stage cp.async on wei/mask/Xh;
// per-tile exp computed once into a double-buffered f16 Es tile (ldsm layout);
// per-row sums kept in registers (rows are thread-invariant), normalized in
// the epilogue.
__global__ __launch_bounds__(256) void sav_mma(const int* __restrict__ mask,
                                               float* __restrict__ out)
{
    __shared__ float  Ws[3][32][36];   // wei f32 tile, 144B stride
    __shared__ int    Ms[3][32][36];   // mask tile
    __shared__ __half Bs[3][32][72];   // Xh tile (trans-ldsm layout, proven)
    __shared__ __half Es[2][32][40];   // exp(f16) tile, ldsm layout (80B stride)
    __shared__ float  rowsum_sh[32];

    const int b  = blockIdx.z;
    const int bn = blockIdx.x * 64;   // d
    const int bm = blockIdx.y * 32;   // q
    const float* Wrow = g_wei + ((b * NN + bm) << 9);        // [32][512]
    const int*   Mrow = mask  + (b * NN + bm) * NN;
    const __half* Bx  = g_xh + b * NN * DD;

    const int tid = threadIdx.x, warp = tid >> 5, lane = tid & 31;
    const int wm = warp >> 2, wn = warp & 3;   // warp tile 16x16 (2x4)
    const int gq = lane >> 2, tq = lane & 3;

    const int er = tid >> 3, ec = (tid & 7) * 4;   // exp coords: row, 4 cols
    const int br = tid >> 3, bq = tid & 7;         // B stage coords

    float acc[2][4] = {};
    float rsum = 0.f;

    // prologue: stages 0,1
    #pragma unroll
    for (int s = 0; s < 2; s++) {
        int nk = s * 32;
        cp16(&Ws[s][er][ec], &Wrow[(er << 9) + nk + ec]);
        cp16(&Ms[s][er][ec], &Mrow[(er << 9) + nk + ec]);
        cp16(&Bs[s][br][bq * 8], &Bx[(nk + br) * DD + bn + bq * 8]);
        CP_COMMIT();
    }

    int cur = 0;
    #pragma unroll 1
    for (int it = 0; it < 16; it++) {
        CP_WAIT1();
        __syncthreads();
        if (it < 14) {
            int nk = (it + 2) * 32;
            int s  = (it + 2) % 3;
            cp16(&Ws[s][er][ec], &Wrow[(er << 9) + nk + ec]);
            cp16(&Ms[s][er][ec], &Mrow[(er << 9) + nk + ec]);
            cp16(&Bs[s][br][bq * 8], &Bx[(nk + br) * DD + bn + bq * 8]);
            CP_COMMIT();
        }
        const int eb = it & 1;

        // exp tile: 4 elements per thread, accumulate row partials
        {
            float4 sv = *(const float4*)&Ws[cur][er][ec];
            int4   mv = *(const int4*)  &Ms[cur][er][ec];
            float e0 = (mv.x != 0) ? __expf(sv.x) : 0.f;
            float e1 = (mv.y != 0) ? __expf(sv.y) : 0.f;
            float e2 = (mv.z != 0) ? __expf(sv.z) : 0.f;
            float e3 = (mv.w != 0) ? __expf(sv.w) : 0.f;
            rsum += (e0 + e1) + (e2 + e3);
            __half2 h01 = __floats2half2_rn(e0, e1);
            __half2 h23 = __floats2half2_rn(e2, e3);
            uint2 o;
            o.x = *reinterpret_cast<unsigned*>(&h01);
            o.y = *reinterpret_cast<unsigned*>(&h23);
            *(uint2*)&Es[eb][er][ec] = o;
        }
        __syncthreads();

        #pragma unroll
        for (int ks = 0; ks < 2; ks++) {
            int kc = ks * 16;
            unsigned a[4], bf[4];
            {
                int r = wm * 16 + (lane & 15);
                int c = kc + 8 * (lane >> 4);
                ldsm_x4(a, &Es[eb][r][c]);
            }
            {
                int kr = kc + (lane & 7) + 8 * ((lane >> 3) & 1);
                int nc = wn * 16 + 8 * (lane >> 4);
                ldsm_x4_trans(bf, &Bs[cur][kr][nc]);
            }
            #pragma unroll
            for (int tn8 = 0; tn8 < 2; tn8++)
                mma16816(acc[tn8], a, bf[tn8 * 2], bf[tn8 * 2 + 1]);
        }
        cur = (cur + 1) % 3;
        __syncthreads();
    }

    // row-sum reduction: 8 threads per row (same warp, lane group of 8)
    rsum += __shfl_xor_sync(0xffffffffu, rsum, 1);
    rsum += __shfl_xor_sync(0xffffffffu, rsum, 2);
    rsum += __shfl_xor_sync(0xffffffffu, rsum, 4);
    if ((tid & 7) == 0) rowsum_sh[er] = rsum;
    __syncthreads();

    {
        int lr0 = wm * 16 + gq;
        float inv0 = 1.0f / rowsum_sh[lr0];
        float inv1 = 1.0f / rowsum_sh[lr0 + 8];
        #pragma unroll
        for (int tn8 = 0; tn8 < 2; tn8++) {
            int c  = bn + wn * 16 + tn8 * 8 + 2 * tq;
            int r0 = bm + lr0;
            *(float2*)&out[(b * NN + r0) * DD + c] =
                make_float2(acc[tn8][0] * inv0, acc[tn8][1] * inv0);
            *(float2*)&out[(b * NN + r0 + 8) * DD + c] =
                make_float2(acc[tn8][2] * inv1, acc[tn8][3] * inv1);
        }
    }
}

// ---------------- launcher ---------------------------------------------------
extern "C" void kernel_launch(void* const* d_in, const int* in_sizes, int n_in,
                              void* d_out, int out_size)
{
    const float* X    = (const float*)d_in[0];  // [4,512,256]
    const int*   mask = (const int*)  d_in[1];  // [4,512,512]
    const float* Wa_w = (const float*)d_in[2];  // [256,256]
    const float* Wa_b = (const float*)d_in[3];  // [256]
    const float* Ua_w = (const float*)d_in[4];  // [256,256]
    const float* Ua_b = (const float*)d_in[5];  // [256]
    const float* Va_w = (const float*)d_in[6];  // [1,256]
    // d_in[7] = Va_b : softmax-invariant constant -> unused

    (void)in_sizes; (void)n_in; (void)out_size;

    conv_kernel<<<640, 256>>>((const float4*)X, (const float4*)Wa_w,
                              (const float4*)Ua_w);

    dim3 pgrid(DD / 64, (BB * NN) / 128, 2);    // 128 blocks
    proj_mma<<<pgrid, 256>>>(Wa_b, Ua_b);

    dim3 sgrid(NN / KT, NN / QB, BB);           // 512 blocks
    score_kernel<<<sgrid, 256>>>(Va_w);

    dim3 agrid(DD / 64, NN / 32, BB);           // 4 x 16 x 4 = 256 blocks
    sav_mma<<<agrid, 256>>>(mask, (float*)d_out);
}